// round 1
// baseline (speedup 1.0000x reference)
#include <cuda_runtime.h>
#include <cstddef>

// ---------------------------------------------------------------------------
// TurboQuantMSE: y = x @ Pi^T ; idx = nearest-centroid(y) ; x_hat = c[idx] @ Pi
// Baseline: fp32 SIMT SGEMM (128x128x8, 8x8/thread, double-buffered smem),
// quantization fused into GEMM1 epilogue. Accuracy requirement: GEMM1 must be
// fp32-accurate (index flips at quantization boundaries dominate rel_err).
// ---------------------------------------------------------------------------

namespace {
constexpr int N_ = 4096;   // rows of x
constexpr int D_ = 4096;   // dim / rotation size
constexpr int BM = 128;
constexpr int BN = 128;
constexpr int BK = 8;
constexpr int NTHREADS = 256;
}

// Scratch for quantized-reconstructed y (allocation-free rule: device global).
__device__ float g_yhat[(size_t)N_ * D_];

// ---------------------------------------------------------------------------
// GEMM1 (NT): y[n,k] = sum_d x[n,d] * Pi[k,d], fused 16-level quantization.
// Writes g_yhat = centroids[idx] and idxf = (float)idx.
// ---------------------------------------------------------------------------
__global__ __launch_bounds__(NTHREADS, 2)
void gemm1_nt_quant(const float* __restrict__ A,    // x [N_, D_]
                    const float* __restrict__ B,    // Pi [D_, D_] (k-major rows)
                    const float* __restrict__ cent, // [16]
                    float* __restrict__ idxf,       // [N_, D_] float indices
                    int write_idx)
{
    __shared__ float As[2][BK][BM];
    __shared__ float Bs[2][BK][BN];
    __shared__ float s_cent[16];
    __shared__ float s_bound[15];

    const int tid = threadIdx.x;
    if (tid < 16) s_cent[tid] = cent[tid];
    if (tid < 15) s_bound[tid] = 0.5f * (cent[tid] + cent[tid + 1]);

    const int bm = blockIdx.y * BM;
    const int bn = blockIdx.x * BN;

    // global->smem load mapping: 128 rows x 8 k-cols per tile, float4 loads
    const int lrow = tid >> 1;           // 0..127
    const int lcol = (tid & 1) << 2;     // 0 or 4

    const float* Ap = A + (size_t)(bm + lrow) * D_ + lcol;
    const float* Bp = B + (size_t)(bn + lrow) * D_ + lcol;

    // compute mapping: 8x8 per thread
    const int trow = (tid >> 4) << 3;    // 0..120
    const int tcol = (tid & 15) << 3;    // 0..120

    float acc[8][8];
#pragma unroll
    for (int i = 0; i < 8; ++i)
#pragma unroll
        for (int j = 0; j < 8; ++j) acc[i][j] = 0.0f;

    float4 a4 = *(const float4*)(Ap);
    float4 b4 = *(const float4*)(Bp);
    int buf = 0;
    As[buf][lcol + 0][lrow] = a4.x; As[buf][lcol + 1][lrow] = a4.y;
    As[buf][lcol + 2][lrow] = a4.z; As[buf][lcol + 3][lrow] = a4.w;
    Bs[buf][lcol + 0][lrow] = b4.x; Bs[buf][lcol + 1][lrow] = b4.y;
    Bs[buf][lcol + 2][lrow] = b4.z; Bs[buf][lcol + 3][lrow] = b4.w;
    __syncthreads();

    for (int t = 1; t < D_ / BK; ++t) {
        a4 = *(const float4*)(Ap + t * BK);
        b4 = *(const float4*)(Bp + t * BK);
#pragma unroll
        for (int kk = 0; kk < BK; ++kk) {
            float ra[8], rb[8];
            *(float4*)(ra)     = *(const float4*)(&As[buf][kk][trow]);
            *(float4*)(ra + 4) = *(const float4*)(&As[buf][kk][trow + 4]);
            *(float4*)(rb)     = *(const float4*)(&Bs[buf][kk][tcol]);
            *(float4*)(rb + 4) = *(const float4*)(&Bs[buf][kk][tcol + 4]);
#pragma unroll
            for (int i = 0; i < 8; ++i)
#pragma unroll
                for (int j = 0; j < 8; ++j)
                    acc[i][j] = fmaf(ra[i], rb[j], acc[i][j]);
        }
        buf ^= 1;
        As[buf][lcol + 0][lrow] = a4.x; As[buf][lcol + 1][lrow] = a4.y;
        As[buf][lcol + 2][lrow] = a4.z; As[buf][lcol + 3][lrow] = a4.w;
        Bs[buf][lcol + 0][lrow] = b4.x; Bs[buf][lcol + 1][lrow] = b4.y;
        Bs[buf][lcol + 2][lrow] = b4.z; Bs[buf][lcol + 3][lrow] = b4.w;
        __syncthreads();
    }
    // last tile
#pragma unroll
    for (int kk = 0; kk < BK; ++kk) {
        float ra[8], rb[8];
        *(float4*)(ra)     = *(const float4*)(&As[buf][kk][trow]);
        *(float4*)(ra + 4) = *(const float4*)(&As[buf][kk][trow + 4]);
        *(float4*)(rb)     = *(const float4*)(&Bs[buf][kk][tcol]);
        *(float4*)(rb + 4) = *(const float4*)(&Bs[buf][kk][tcol + 4]);
#pragma unroll
        for (int i = 0; i < 8; ++i)
#pragma unroll
            for (int j = 0; j < 8; ++j)
                acc[i][j] = fmaf(ra[i], rb[j], acc[i][j]);
    }

    // epilogue: quantize. idx = sum(v > bound_b); strict '>' matches
    // jnp.argmin first-occurrence tie rule at exact midpoints.
#pragma unroll
    for (int i = 0; i < 8; ++i) {
        const size_t rowoff = (size_t)(bm + trow + i) * D_ + bn + tcol;
#pragma unroll
        for (int jv = 0; jv < 2; ++jv) {
            float4 yh, qf;
            float* yhp = (float*)&yh;
            float* qfp = (float*)&qf;
#pragma unroll
            for (int j = 0; j < 4; ++j) {
                float v = acc[i][jv * 4 + j];
                int q = 0;
#pragma unroll
                for (int b = 0; b < 15; ++b) q += (v > s_bound[b]) ? 1 : 0;
                yhp[j] = s_cent[q];
                qfp[j] = (float)q;
            }
            *(float4*)(g_yhat + rowoff + jv * 4) = yh;
            if (write_idx) *(float4*)(idxf + rowoff + jv * 4) = qf;
        }
    }
}

// ---------------------------------------------------------------------------
// GEMM2 (NN): x_hat[n,d] = sum_k g_yhat[n,k] * Pi[k,d]
// ---------------------------------------------------------------------------
__global__ __launch_bounds__(NTHREADS, 2)
void gemm2_nn(const float* __restrict__ B,   // Pi [D_, D_]
              float* __restrict__ C)         // x_hat [N_, D_]
{
    const float* A = g_yhat;
    __shared__ float As[2][BK][BM];
    __shared__ float Bs[2][BK][BN];

    const int tid = threadIdx.x;
    const int bm = blockIdx.y * BM;
    const int bn = blockIdx.x * BN;

    const int larow = tid >> 1;          // 0..127
    const int lacol = (tid & 1) << 2;    // 0 or 4
    const int lbrow = tid >> 5;          // 0..7
    const int lbcol = (tid & 31) << 2;   // 0..124

    const float* Ap = A + (size_t)(bm + larow) * D_ + lacol;
    const float* Bp = B + (size_t)lbrow * D_ + bn + lbcol;

    const int trow = (tid >> 4) << 3;
    const int tcol = (tid & 15) << 3;

    float acc[8][8];
#pragma unroll
    for (int i = 0; i < 8; ++i)
#pragma unroll
        for (int j = 0; j < 8; ++j) acc[i][j] = 0.0f;

    float4 a4 = *(const float4*)(Ap);
    float4 b4 = *(const float4*)(Bp);
    int buf = 0;
    As[buf][lacol + 0][larow] = a4.x; As[buf][lacol + 1][larow] = a4.y;
    As[buf][lacol + 2][larow] = a4.z; As[buf][lacol + 3][larow] = a4.w;
    *(float4*)(&Bs[buf][lbrow][lbcol]) = b4;
    __syncthreads();

    for (int t = 1; t < D_ / BK; ++t) {
        a4 = *(const float4*)(Ap + t * BK);
        b4 = *(const float4*)(Bp + (size_t)t * BK * D_);
#pragma unroll
        for (int kk = 0; kk < BK; ++kk) {
            float ra[8], rb[8];
            *(float4*)(ra)     = *(const float4*)(&As[buf][kk][trow]);
            *(float4*)(ra + 4) = *(const float4*)(&As[buf][kk][trow + 4]);
            *(float4*)(rb)     = *(const float4*)(&Bs[buf][kk][tcol]);
            *(float4*)(rb + 4) = *(const float4*)(&Bs[buf][kk][tcol + 4]);
#pragma unroll
            for (int i = 0; i < 8; ++i)
#pragma unroll
                for (int j = 0; j < 8; ++j)
                    acc[i][j] = fmaf(ra[i], rb[j], acc[i][j]);
        }
        buf ^= 1;
        As[buf][lacol + 0][larow] = a4.x; As[buf][lacol + 1][larow] = a4.y;
        As[buf][lacol + 2][larow] = a4.z; As[buf][lacol + 3][larow] = a4.w;
        *(float4*)(&Bs[buf][lbrow][lbcol]) = b4;
        __syncthreads();
    }
#pragma unroll
    for (int kk = 0; kk < BK; ++kk) {
        float ra[8], rb[8];
        *(float4*)(ra)     = *(const float4*)(&As[buf][kk][trow]);
        *(float4*)(ra + 4) = *(const float4*)(&As[buf][kk][trow + 4]);
        *(float4*)(rb)     = *(const float4*)(&Bs[buf][kk][tcol]);
        *(float4*)(rb + 4) = *(const float4*)(&Bs[buf][kk][tcol + 4]);
#pragma unroll
        for (int i = 0; i < 8; ++i)
#pragma unroll
            for (int j = 0; j < 8; ++j)
                acc[i][j] = fmaf(ra[i], rb[j], acc[i][j]);
    }

#pragma unroll
    for (int i = 0; i < 8; ++i) {
        const size_t rowoff = (size_t)(bm + trow + i) * D_ + bn + tcol;
#pragma unroll
        for (int jv = 0; jv < 2; ++jv) {
            float4 v;
            float* vp = (float*)&v;
#pragma unroll
            for (int j = 0; j < 4; ++j) vp[j] = acc[i][jv * 4 + j];
            *(float4*)(C + rowoff + jv * 4) = v;
        }
    }
}

// ---------------------------------------------------------------------------
// kernel_launch: inputs per metadata order: x [N*D] f32, Pi [D*D] f32,
// centroids [16] f32. Output assumed: x_hat (N*D floats) then indices
// (N*D floats) concatenated.
// ---------------------------------------------------------------------------
extern "C" void kernel_launch(void* const* d_in, const int* in_sizes, int n_in,
                              void* d_out, int out_size)
{
    const float* x    = (const float*)d_in[0];
    const float* Pi   = (const float*)d_in[1];
    const float* cent = (const float*)d_in[2];

    float* out  = (float*)d_out;
    float* xhat = out;
    float* idxf = out + (size_t)N_ * D_;

    const long long total = (long long)N_ * D_;
    const int write_idx = ((long long)out_size >= 2 * total) ? 1 : 0;

    dim3 grid(D_ / BN, N_ / BM);
    dim3 block(NTHREADS);

    gemm1_nt_quant<<<grid, block>>>(x, Pi, cent, idxf, write_idx);
    gemm2_nn<<<grid, block>>>(Pi, xhat);
}

// round 5
// speedup vs baseline: 3.0543x; 3.0543x over previous
#include <cuda_runtime.h>
#include <cuda_fp16.h>
#include <cstdint>
#include <cstddef>

// ============================================================================
// TurboQuantMSE via mma.sync fp16 (HMMA, sm_80 ISA — valid on plain sm_103).
// Operands pre-scaled by 2^10, split hi/lo in fp16 (covers ~22 mantissa bits).
// GEMM1: y' = 2^20 y via 3-product HMMA + fused quantization, with exact
//        fp32 warp-cooperative repair of values within THR of a boundary
//        (tensor-core accumulation bias ~1e-5 rel would otherwise flip them).
// GEMM2: x_hat via 3-product HMMA, /2^20 on store (exact power of 2).
// ============================================================================

#define DEVFN __device__ __forceinline__

namespace {
constexpr int N_  = 4096;
constexpr int D_  = 4096;
constexpr int BM  = 128;
constexpr int BN  = 256;
constexpr int BKE = 64;                 // K elements per chunk (fp16)
constexpr int NCH = D_ / BKE;           // 64 chunks
constexpr int NTH = 256;

constexpr float SCALE   = 1024.0f;             // 2^10, exact
constexpr float YSCALE  = 1048576.0f;          // 2^20, exact
constexpr float INV_YS  = 1.0f / 1048576.0f;   // exact power of two
constexpr float THR     = 8.0f;                // repair threshold in 2^20-scaled y units

constexpr int A_BYTES = BM * 128;       // 16 KB (128 rows x 64 fp16)
constexpr int B_BYTES = BN * 128;       // 32 KB
constexpr int STAGE   = 2 * A_BYTES + 2 * B_BYTES;   // 96 KB
constexpr int SMEM_SZ = 2 * STAGE;                   // 192 KB
}

// -------- device scratch (allocation-free rule: device globals) -------------
__device__ __half g_xhi [(size_t)N_ * D_];
__device__ __half g_xlo [(size_t)N_ * D_];
__device__ __half g_phi [(size_t)D_ * D_];
__device__ __half g_plo [(size_t)D_ * D_];
__device__ __half g_pthi[(size_t)D_ * D_];
__device__ __half g_ptlo[(size_t)D_ * D_];
__device__ __half g_yhhi[(size_t)N_ * D_];
__device__ __half g_yhlo[(size_t)N_ * D_];

// ---------------------------- PTX helpers -----------------------------------
DEVFN uint32_t smem_u32(const void* p) {
    uint32_t a;
    asm("{ .reg .u64 t; cvta.to.shared.u64 t, %1; cvt.u32.u64 %0, t; }" : "=r"(a) : "l"(p));
    return a;
}
DEVFN void cpasync16(uint32_t s, const void* g) {
    asm volatile("cp.async.cg.shared.global [%0], [%1], 16;" :: "r"(s), "l"(g));
}
#define CP_COMMIT() asm volatile("cp.async.commit_group;" ::: "memory")
#define CP_WAIT0()  asm volatile("cp.async.wait_group 0;" ::: "memory")

DEVFN void ldsm4(uint32_t* r, uint32_t addr) {
    asm volatile("ldmatrix.sync.aligned.m8n8.x4.shared.b16 {%0,%1,%2,%3}, [%4];"
                 : "=r"(r[0]), "=r"(r[1]), "=r"(r[2]), "=r"(r[3]) : "r"(addr));
}
DEVFN void mma16816(float* c, const uint32_t* a, const uint32_t* b) {
    asm volatile(
        "mma.sync.aligned.m16n8k16.row.col.f32.f16.f16.f32 "
        "{%0,%1,%2,%3}, {%4,%5,%6,%7}, {%8,%9}, {%0,%1,%2,%3};"
        : "+f"(c[0]), "+f"(c[1]), "+f"(c[2]), "+f"(c[3])
        : "r"(a[0]), "r"(a[1]), "r"(a[2]), "r"(a[3]), "r"(b[0]), "r"(b[1]));
}
DEVFN uint32_t pack2(__half a, __half b) {
    return (uint32_t)__half_as_ushort(a) | ((uint32_t)__half_as_ushort(b) << 16);
}
DEVFN uint32_t swz(uint32_t off) { return off ^ ((off >> 3) & 0x70); }

// ---------------------------- staging loader ---------------------------------
template<int ROWS>
DEVFN void ld_op(uint32_t sdst, const __half* __restrict__ g,
                 int row0, int kc, int tid)
{
    const char* gb = (const char*)g + ((size_t)row0 * D_ + (size_t)kc * BKE) * 2;
    constexpr int NOPS = ROWS * 8;             // 16B ops
#pragma unroll
    for (int i = 0; i < NOPS / NTH; ++i) {
        int idx = tid + i * NTH;
        int r = idx >> 3;
        int c = (idx & 7) << 4;
        cpasync16(sdst + swz((uint32_t)(r * 128 + c)),
                  gb + (size_t)r * (D_ * 2) + c);
    }
}

DEVFN void stage_load(uint32_t sb, int s, int kc,
                      const __half* Ahi, const __half* Alo,
                      const __half* Bhi, const __half* Blo,
                      int bm, int bn, int tid)
{
    const uint32_t st = sb + s * STAGE;
    ld_op<BM>(st,                         Ahi, bm, kc, tid);
    ld_op<BM>(st + A_BYTES,               Alo, bm, kc, tid);
    ld_op<BN>(st + 2 * A_BYTES,           Bhi, bn, kc, tid);
    ld_op<BN>(st + 2 * A_BYTES + B_BYTES, Blo, bn, kc, tid);
}

// --------- warp-cooperative exact fp32 re-computation of y'[row,col] ---------
// All 32 lanes of the warp participate (convergent call). Lanes whose `need`
// is set get their v replaced by an exact fp32 dot (x[row,:] . Pi[col,:]) * 2^20.
DEVFN void repair_warp(float& v, bool need, int row, int col,
                       const float* __restrict__ x, const float* __restrict__ Pi,
                       int lid)
{
    unsigned m = __ballot_sync(0xFFFFFFFFu, need);
    while (m) {
        int src = __ffs(m) - 1;
        m &= m - 1;
        int r = __shfl_sync(0xFFFFFFFFu, row, src);
        int c = __shfl_sync(0xFFFFFFFFu, col, src);
        const float* xr = x  + (size_t)r * D_;
        const float* pr = Pi + (size_t)c * D_;
        float s0 = 0.f, s1 = 0.f, s2 = 0.f, s3 = 0.f;
#pragma unroll 4
        for (int k = lid * 4; k < D_; k += 128) {
            float4 a = *(const float4*)(xr + k);
            float4 b = *(const float4*)(pr + k);
            s0 = fmaf(a.x, b.x, s0); s1 = fmaf(a.y, b.y, s1);
            s2 = fmaf(a.z, b.z, s2); s3 = fmaf(a.w, b.w, s3);
        }
        float part = (s0 + s1) + (s2 + s3);
#pragma unroll
        for (int o = 16; o; o >>= 1) part += __shfl_xor_sync(0xFFFFFFFFu, part, o);
        if (lid == src) v = part * YSCALE;
    }
}

// ---------------------------- main GEMM kernel -------------------------------
// MODE 0: GEMM1 (x, Pi) -> quantize epilogue (+ boundary repair)
// MODE 1: GEMM2 (yhat, PiT) -> fp32 store to xhat (rescaled by 2^-20)
template<int MODE>
__global__ __launch_bounds__(NTH, 1)
void tq_mma(const float* __restrict__ cent, float* __restrict__ out0, int write_idx,
            const float* __restrict__ xf, const float* __restrict__ pif)
{
    extern __shared__ char smem[];
    const uint32_t sb = smem_u32(smem);
    const int tid = threadIdx.x, wid = tid >> 5, lid = tid & 31;
    const int bm = blockIdx.y * BM;
    const int bn = blockIdx.x * BN;

    const __half* Ahi = (MODE == 0) ? g_xhi : g_yhhi;
    const __half* Alo = (MODE == 0) ? g_xlo : g_yhlo;
    const __half* Bhi = (MODE == 0) ? g_phi : g_pthi;
    const __half* Blo = (MODE == 0) ? g_plo : g_ptlo;

    __shared__ float    s_bound[16];    // boundaries scaled by 2^20 (15 used)
    __shared__ uint16_t s_chi[16];      // fp16(2^10 * c)
    __shared__ uint16_t s_clo[16];
    if (MODE == 0) {
        if (tid < 16) {
            float cs = cent[tid] * SCALE;           // exact
            __half h = __float2half_rn(cs);
            s_chi[tid] = __half_as_ushort(h);
            s_clo[tid] = __half_as_ushort(__float2half_rn(cs - __half2float(h)));
        }
        if (tid < 15) s_bound[tid] = (0.5f * (cent[tid] + cent[tid + 1])) * YSCALE;
    }

    // warp tiling: 2 (M) x 4 (N) warps, each 64x64
    const int wm = (wid & 1) * 64;
    const int wn = (wid >> 1) * 64;

    const int a_r = lid & 15;
    const int a_k = (lid >> 4) << 4;
    const int b_r = (lid & 7) | ((lid >> 4) << 3);
    const int b_k = ((lid >> 3) & 1) << 4;

    float acc[4][8][4];
#pragma unroll
    for (int i = 0; i < 4; ++i)
#pragma unroll
        for (int j = 0; j < 8; ++j)
#pragma unroll
            for (int k = 0; k < 4; ++k) acc[i][j][k] = 0.0f;

    stage_load(sb, 0, 0, Ahi, Alo, Bhi, Blo, bm, bn, tid);
    CP_COMMIT();

    for (int t = 0; t < NCH; ++t) {
        CP_WAIT0();
        __syncthreads();
        if (t + 1 < NCH) {
            stage_load(sb, (t + 1) & 1, t + 1, Ahi, Alo, Bhi, Blo, bm, bn, tid);
            CP_COMMIT();
        }
        const uint32_t st  = sb + (t & 1) * STAGE;
        const uint32_t pAh = st;
        const uint32_t pAl = st + A_BYTES;
        const uint32_t pBh = st + 2 * A_BYTES;
        const uint32_t pBl = st + 2 * A_BYTES + B_BYTES;

        uint32_t a[4][4], b[4][4];
#pragma unroll
        for (int kk = 0; kk < 4; ++kk) {
            // ---- hh ----
#pragma unroll
            for (int mt = 0; mt < 4; ++mt)
                ldsm4(a[mt], pAh + swz((uint32_t)((wm + mt * 16 + a_r) * 128 + kk * 32 + a_k)));
#pragma unroll
            for (int g = 0; g < 4; ++g)
                ldsm4(b[g], pBh + swz((uint32_t)((wn + g * 16 + b_r) * 128 + kk * 32 + b_k)));
#pragma unroll
            for (int mt = 0; mt < 4; ++mt)
#pragma unroll
                for (int g = 0; g < 4; ++g) {
                    mma16816(acc[mt][2 * g],     a[mt], &b[g][0]);
                    mma16816(acc[mt][2 * g + 1], a[mt], &b[g][2]);
                }
            // ---- hl ----
#pragma unroll
            for (int g = 0; g < 4; ++g)
                ldsm4(b[g], pBl + swz((uint32_t)((wn + g * 16 + b_r) * 128 + kk * 32 + b_k)));
#pragma unroll
            for (int mt = 0; mt < 4; ++mt)
#pragma unroll
                for (int g = 0; g < 4; ++g) {
                    mma16816(acc[mt][2 * g],     a[mt], &b[g][0]);
                    mma16816(acc[mt][2 * g + 1], a[mt], &b[g][2]);
                }
            // ---- lh ----
#pragma unroll
            for (int mt = 0; mt < 4; ++mt)
                ldsm4(a[mt], pAl + swz((uint32_t)((wm + mt * 16 + a_r) * 128 + kk * 32 + a_k)));
#pragma unroll
            for (int g = 0; g < 4; ++g)
                ldsm4(b[g], pBh + swz((uint32_t)((wn + g * 16 + b_r) * 128 + kk * 32 + b_k)));
#pragma unroll
            for (int mt = 0; mt < 4; ++mt)
#pragma unroll
                for (int g = 0; g < 4; ++g) {
                    mma16816(acc[mt][2 * g],     a[mt], &b[g][0]);
                    mma16816(acc[mt][2 * g + 1], a[mt], &b[g][2]);
                }
        }
        __syncthreads();
    }

    // ------------------------------ epilogue ---------------------------------
    const int erow = (lid >> 2);
    const int ecol = (lid & 3) * 2;

    if (MODE == 1) {
#pragma unroll
        for (int mt = 0; mt < 4; ++mt) {
#pragma unroll
            for (int nt = 0; nt < 8; ++nt) {
                const int col = bn + wn + nt * 8 + ecol;
                const int r0  = bm + wm + mt * 16 + erow;
                float2 v0 = make_float2(acc[mt][nt][0] * INV_YS, acc[mt][nt][1] * INV_YS);
                float2 v1 = make_float2(acc[mt][nt][2] * INV_YS, acc[mt][nt][3] * INV_YS);
                *(float2*)(out0 + (size_t)r0 * D_ + col)       = v0;
                *(float2*)(out0 + (size_t)(r0 + 8) * D_ + col) = v1;
            }
        }
    } else {
        __syncthreads();
        float bnd[15];
#pragma unroll
        for (int b0 = 0; b0 < 15; ++b0) bnd[b0] = s_bound[b0];
#pragma unroll
        for (int mt = 0; mt < 4; ++mt) {
#pragma unroll
            for (int nt = 0; nt < 8; ++nt) {
                const int col = bn + wn + nt * 8 + ecol;
#pragma unroll
                for (int half = 0; half < 2; ++half) {
                    const int r0 = bm + wm + mt * 16 + erow + half * 8;
                    float v0 = acc[mt][nt][half * 2 + 0];  // scaled y' = 2^20 y
                    float v1 = acc[mt][nt][half * 2 + 1];
                    int q0 = 0, q1 = 0;
#pragma unroll
                    for (int b0 = 0; b0 < 15; ++b0) {
                        q0 += (v0 > bnd[b0]) ? 1 : 0;
                        q1 += (v1 > bnd[b0]) ? 1 : 0;
                    }
                    // boundary proximity check (dynamic index -> shared mem)
                    float dl0 = (q0 > 0)  ? v0 - s_bound[q0 - 1] : 1e30f;
                    float dr0 = (q0 < 15) ? s_bound[q0] - v0     : 1e30f;
                    float dl1 = (q1 > 0)  ? v1 - s_bound[q1 - 1] : 1e30f;
                    float dr1 = (q1 < 15) ? s_bound[q1] - v1     : 1e30f;
                    bool n0 = fminf(dl0, dr0) < THR;
                    bool n1 = fminf(dl1, dr1) < THR;
                    repair_warp(v0, n0, r0, col,     xf, pif, lid);
                    repair_warp(v1, n1, r0, col + 1, xf, pif, lid);
                    if (n0) {
                        q0 = 0;
#pragma unroll
                        for (int b0 = 0; b0 < 15; ++b0) q0 += (v0 > bnd[b0]) ? 1 : 0;
                    }
                    if (n1) {
                        q1 = 0;
#pragma unroll
                        for (int b0 = 0; b0 < 15; ++b0) q1 += (v1 > bnd[b0]) ? 1 : 0;
                    }
                    const size_t off = (size_t)r0 * D_ + col;
                    *(uint32_t*)(g_yhhi + off) =
                        (uint32_t)s_chi[q0] | ((uint32_t)s_chi[q1] << 16);
                    *(uint32_t*)(g_yhlo + off) =
                        (uint32_t)s_clo[q0] | ((uint32_t)s_clo[q1] << 16);
                    if (write_idx) {
                        float2 f = make_float2((float)q0, (float)q1);
                        *(float2*)(out0 + off) = f;
                    }
                }
            }
        }
    }
}

// ---------------------------- prep kernels -----------------------------------
__global__ __launch_bounds__(256)
void k_split(const float* __restrict__ src,
             __half* __restrict__ hi, __half* __restrict__ lo)
{
    const size_t i = ((size_t)blockIdx.x * 256 + threadIdx.x) * 4;
    float4 v = *(const float4*)(src + i);
    float s0 = v.x * SCALE, s1 = v.y * SCALE, s2 = v.z * SCALE, s3 = v.w * SCALE;
    __half h0 = __float2half_rn(s0), h1 = __float2half_rn(s1);
    __half h2 = __float2half_rn(s2), h3 = __float2half_rn(s3);
    __half l0 = __float2half_rn(s0 - __half2float(h0));
    __half l1 = __float2half_rn(s1 - __half2float(h1));
    __half l2 = __float2half_rn(s2 - __half2float(h2));
    __half l3 = __float2half_rn(s3 - __half2float(h3));
    uint2 uh; uh.x = pack2(h0, h1); uh.y = pack2(h2, h3);
    uint2 ul; ul.x = pack2(l0, l1); ul.y = pack2(l2, l3);
    *(uint2*)(hi + i) = uh;
    *(uint2*)(lo + i) = ul;
}

__global__ __launch_bounds__(256)
void k_tsplit(const float* __restrict__ Pi)
{
    __shared__ float tile[32][33];
    const int bx = blockIdx.x * 32, by = blockIdx.y * 32;
    const int tx = threadIdx.x & 31, ty = threadIdx.x >> 5;
#pragma unroll
    for (int r = 0; r < 4; ++r)
        tile[ty + r * 8][tx] = Pi[(size_t)(by + ty + r * 8) * D_ + bx + tx];
    __syncthreads();
#pragma unroll
    for (int r = 0; r < 4; ++r) {
        float v = tile[tx][ty + r * 8] * SCALE;
        __half h = __float2half_rn(v);
        __half l = __float2half_rn(v - __half2float(h));
        const size_t o = (size_t)(bx + ty + r * 8) * D_ + by + tx;
        g_pthi[o] = h;
        g_ptlo[o] = l;
    }
}

// ---------------------------- launch ------------------------------------------
extern "C" void kernel_launch(void* const* d_in, const int* in_sizes, int n_in,
                              void* d_out, int out_size)
{
    const float* x    = (const float*)d_in[0];
    const float* Pi   = (const float*)d_in[1];
    const float* cent = (const float*)d_in[2];

    float* out  = (float*)d_out;
    float* xhat = out;
    float* idxf = out + (size_t)N_ * D_;

    const long long total = (long long)N_ * D_;
    const int write_idx = ((long long)out_size >= 2 * total) ? 1 : 0;

    cudaFuncSetAttribute(tq_mma<0>, cudaFuncAttributeMaxDynamicSharedMemorySize, SMEM_SZ);
    cudaFuncSetAttribute(tq_mma<1>, cudaFuncAttributeMaxDynamicSharedMemorySize, SMEM_SZ);

    __half *xhi_p, *xlo_p, *phi_p, *plo_p;
    cudaGetSymbolAddress((void**)&xhi_p, g_xhi);
    cudaGetSymbolAddress((void**)&xlo_p, g_xlo);
    cudaGetSymbolAddress((void**)&phi_p, g_phi);
    cudaGetSymbolAddress((void**)&plo_p, g_plo);

    const int nblk = (int)(total / (4 * 256));                 // 16384
    k_split<<<nblk, 256>>>(x,  xhi_p, xlo_p);
    k_split<<<nblk, 256>>>(Pi, phi_p, plo_p);
    k_tsplit<<<dim3(D_ / 32, D_ / 32), 256>>>(Pi);

    dim3 grid(D_ / BN, N_ / BM);   // (16, 32)
    tq_mma<0><<<grid, NTH, SMEM_SZ>>>(cent, idxf, write_idx, x, Pi);
    tq_mma<1><<<grid, NTH, SMEM_SZ>>>(nullptr, xhat, 0, x, Pi);
}

// round 6
// speedup vs baseline: 4.0468x; 1.3250x over previous
#include <cuda_runtime.h>
#include <cuda_fp16.h>
#include <cstdint>
#include <cstddef>

// ============================================================================
// TurboQuantMSE via mma.sync fp16 (HMMA, sm_80 ISA — valid on plain sm_103).
// GEMM1 (3-product split-fp16, scaled 2^10): y' = 2^20 y, fused quantization,
//   + exact fp32 warp-cooperative repair of boundary-adjacent values.
// GEMM2 (1-product fp16-hi only): x_hat = yhat_hi @ PiT_hi / 2^20.
//   Operand-rounding error ~2.0e-4 rel, within budget vs 1e-3 threshold.
// 512 threads/CTA (16 warps) to cure the issue-rate bottleneck seen in ncu.
// ============================================================================

#define DEVFN __device__ __forceinline__

namespace {
constexpr int N_  = 4096;
constexpr int D_  = 4096;
constexpr int BM  = 128;
constexpr int BN  = 256;
constexpr int BKE = 64;                 // K elements per chunk (fp16)
constexpr int NCH = D_ / BKE;           // 64 chunks
constexpr int NTH = 512;                // 16 warps

constexpr float SCALE   = 1024.0f;             // 2^10, exact
constexpr float YSCALE  = 1048576.0f;          // 2^20, exact
constexpr float INV_YS  = 1.0f / 1048576.0f;   // exact power of two
constexpr float THR     = 8.0f;                // repair threshold (scaled units)

constexpr int A_BYTES = BM * 128;       // 16 KB
constexpr int B_BYTES = BN * 128;       // 32 KB
constexpr int STAGE3  = 2 * A_BYTES + 2 * B_BYTES;   // 96 KB (GEMM1)
constexpr int STAGE1  = A_BYTES + B_BYTES;           // 48 KB (GEMM2)
constexpr int SMEM3   = 2 * STAGE3;                  // 192 KB
constexpr int SMEM1   = 2 * STAGE1;                  // 96 KB
}

// -------- device scratch (allocation-free rule: device globals) -------------
__device__ __half g_xhi [(size_t)N_ * D_];
__device__ __half g_xlo [(size_t)N_ * D_];
__device__ __half g_phi [(size_t)D_ * D_];
__device__ __half g_plo [(size_t)D_ * D_];
__device__ __half g_pthi[(size_t)D_ * D_];
__device__ __half g_yhhi[(size_t)N_ * D_];

// ---------------------------- PTX helpers -----------------------------------
DEVFN uint32_t smem_u32(const void* p) {
    uint32_t a;
    asm("{ .reg .u64 t; cvta.to.shared.u64 t, %1; cvt.u32.u64 %0, t; }" : "=r"(a) : "l"(p));
    return a;
}
DEVFN void cpasync16(uint32_t s, const void* g) {
    asm volatile("cp.async.cg.shared.global [%0], [%1], 16;" :: "r"(s), "l"(g));
}
#define CP_COMMIT() asm volatile("cp.async.commit_group;" ::: "memory")
#define CP_WAIT0()  asm volatile("cp.async.wait_group 0;" ::: "memory")

DEVFN void ldsm4(uint32_t* r, uint32_t addr) {
    asm volatile("ldmatrix.sync.aligned.m8n8.x4.shared.b16 {%0,%1,%2,%3}, [%4];"
                 : "=r"(r[0]), "=r"(r[1]), "=r"(r[2]), "=r"(r[3]) : "r"(addr));
}
DEVFN void mma16816(float* c, const uint32_t* a, const uint32_t* b) {
    asm volatile(
        "mma.sync.aligned.m16n8k16.row.col.f32.f16.f16.f32 "
        "{%0,%1,%2,%3}, {%4,%5,%6,%7}, {%8,%9}, {%0,%1,%2,%3};"
        : "+f"(c[0]), "+f"(c[1]), "+f"(c[2]), "+f"(c[3])
        : "r"(a[0]), "r"(a[1]), "r"(a[2]), "r"(a[3]), "r"(b[0]), "r"(b[1]));
}
DEVFN uint32_t pack2(__half a, __half b) {
    return (uint32_t)__half_as_ushort(a) | ((uint32_t)__half_as_ushort(b) << 16);
}
DEVFN uint32_t swz(uint32_t off) { return off ^ ((off >> 3) & 0x70); }

// ---------------------------- staging loader ---------------------------------
template<int ROWS>
DEVFN void ld_op(uint32_t sdst, const __half* __restrict__ g,
                 int row0, int kc, int tid)
{
    const char* gb = (const char*)g + ((size_t)row0 * D_ + (size_t)kc * BKE) * 2;
    constexpr int NOPS = ROWS * 8;             // 16B ops
#pragma unroll
    for (int i = 0; i < NOPS / NTH; ++i) {
        int idx = tid + i * NTH;
        int r = idx >> 3;
        int c = (idx & 7) << 4;
        cpasync16(sdst + swz((uint32_t)(r * 128 + c)),
                  gb + (size_t)r * (D_ * 2) + c);
    }
}

// --------- warp-cooperative exact fp32 re-computation of y'[row,col] ---------
DEVFN void repair_warp(float& v, bool need, int row, int col,
                       const float* __restrict__ x, const float* __restrict__ Pi,
                       int lid)
{
    unsigned m = __ballot_sync(0xFFFFFFFFu, need);
    while (m) {
        int src = __ffs(m) - 1;
        m &= m - 1;
        int r = __shfl_sync(0xFFFFFFFFu, row, src);
        int c = __shfl_sync(0xFFFFFFFFu, col, src);
        const float* xr = x  + (size_t)r * D_;
        const float* pr = Pi + (size_t)c * D_;
        float s0 = 0.f, s1 = 0.f, s2 = 0.f, s3 = 0.f;
#pragma unroll 4
        for (int k = lid * 4; k < D_; k += 128) {
            float4 a = *(const float4*)(xr + k);
            float4 b = *(const float4*)(pr + k);
            s0 = fmaf(a.x, b.x, s0); s1 = fmaf(a.y, b.y, s1);
            s2 = fmaf(a.z, b.z, s2); s3 = fmaf(a.w, b.w, s3);
        }
        float part = (s0 + s1) + (s2 + s3);
#pragma unroll
        for (int o = 16; o; o >>= 1) part += __shfl_xor_sync(0xFFFFFFFFu, part, o);
        if (lid == src) v = part * YSCALE;
    }
}

// ---------------------------- main GEMM kernel -------------------------------
// MODE 0: GEMM1, 3 products (x hi/lo, Pi hi/lo) -> quantize + repair epilogue
// MODE 1: GEMM2, 1 product (yhat_hi, PiT_hi)   -> fp32 store * 2^-20
template<int MODE>
__global__ __launch_bounds__(NTH, 1)
void tq_mma(const float* __restrict__ cent, float* __restrict__ out0, int write_idx,
            const float* __restrict__ xf, const float* __restrict__ pif)
{
    extern __shared__ char smem[];
    const uint32_t sb = smem_u32(smem);
    const int tid = threadIdx.x, wid = tid >> 5, lid = tid & 31;
    const int bm = blockIdx.y * BM;
    const int bn = blockIdx.x * BN;

    constexpr int STG = (MODE == 0) ? STAGE3 : STAGE1;

    const __half* Ahi = (MODE == 0) ? g_xhi : g_yhhi;
    const __half* Bhi = (MODE == 0) ? g_phi : g_pthi;

    __shared__ float    s_bound[16];
    __shared__ uint16_t s_chi[16];
    if (MODE == 0) {
        if (tid < 16) {
            float cs = cent[tid] * SCALE;           // exact
            s_chi[tid] = __half_as_ushort(__float2half_rn(cs));
        }
        if (tid < 15) s_bound[tid] = (0.5f * (cent[tid] + cent[tid + 1])) * YSCALE;
    }

    // 16 warps: 4 (M) x 4 (N), each 32x64
    const int wm = (wid & 3) * 32;
    const int wn = (wid >> 2) * 64;

    const int a_r = lid & 15;
    const int a_k = (lid >> 4) << 4;
    const int b_r = (lid & 7) | ((lid >> 4) << 3);
    const int b_k = ((lid >> 3) & 1) << 4;

    float acc[2][8][4];
#pragma unroll
    for (int i = 0; i < 2; ++i)
#pragma unroll
        for (int j = 0; j < 8; ++j)
#pragma unroll
            for (int k = 0; k < 4; ++k) acc[i][j][k] = 0.0f;

    // prime stage 0
    {
        const uint32_t st = sb;
        ld_op<BM>(st, Ahi, bm, 0, tid);
        if (MODE == 0) {
            ld_op<BM>(st + A_BYTES,               g_xlo, bm, 0, tid);
            ld_op<BN>(st + 2 * A_BYTES,           Bhi,   bn, 0, tid);
            ld_op<BN>(st + 2 * A_BYTES + B_BYTES, g_plo, bn, 0, tid);
        } else {
            ld_op<BN>(st + A_BYTES, Bhi, bn, 0, tid);
        }
    }
    CP_COMMIT();

    for (int t = 0; t < NCH; ++t) {
        CP_WAIT0();
        __syncthreads();
        if (t + 1 < NCH) {
            const uint32_t st = sb + ((t + 1) & 1) * STG;
            ld_op<BM>(st, Ahi, bm, t + 1, tid);
            if (MODE == 0) {
                ld_op<BM>(st + A_BYTES,               g_xlo, bm, t + 1, tid);
                ld_op<BN>(st + 2 * A_BYTES,           Bhi,   bn, t + 1, tid);
                ld_op<BN>(st + 2 * A_BYTES + B_BYTES, g_plo, bn, t + 1, tid);
            } else {
                ld_op<BN>(st + A_BYTES, Bhi, bn, t + 1, tid);
            }
            CP_COMMIT();
        }
        const uint32_t st  = sb + (t & 1) * STG;
        const uint32_t pAh = st;
        const uint32_t pAl = st + A_BYTES;                     // MODE 0 only
        const uint32_t pBh = (MODE == 0) ? st + 2 * A_BYTES : st + A_BYTES;
        const uint32_t pBl = st + 2 * A_BYTES + B_BYTES;       // MODE 0 only

        uint32_t a[2][4], bh[4][4];
#pragma unroll
        for (int kk = 0; kk < 4; ++kk) {
            // ---- load A_hi + B_hi, run hh ----
#pragma unroll
            for (int mt = 0; mt < 2; ++mt)
                ldsm4(a[mt], pAh + swz((uint32_t)((wm + mt * 16 + a_r) * 128 + kk * 32 + a_k)));
#pragma unroll
            for (int g = 0; g < 4; ++g)
                ldsm4(bh[g], pBh + swz((uint32_t)((wn + g * 16 + b_r) * 128 + kk * 32 + b_k)));
#pragma unroll
            for (int mt = 0; mt < 2; ++mt)
#pragma unroll
                for (int g = 0; g < 4; ++g) {
                    mma16816(acc[mt][2 * g],     a[mt], &bh[g][0]);
                    mma16816(acc[mt][2 * g + 1], a[mt], &bh[g][2]);
                }
            if (MODE == 0) {
                // ---- load B_lo, run hl (A_hi reused) ----
                uint32_t bl[4][4];
#pragma unroll
                for (int g = 0; g < 4; ++g)
                    ldsm4(bl[g], pBl + swz((uint32_t)((wn + g * 16 + b_r) * 128 + kk * 32 + b_k)));
#pragma unroll
                for (int mt = 0; mt < 2; ++mt)
#pragma unroll
                    for (int g = 0; g < 4; ++g) {
                        mma16816(acc[mt][2 * g],     a[mt], &bl[g][0]);
                        mma16816(acc[mt][2 * g + 1], a[mt], &bl[g][2]);
                    }
                // ---- load A_lo, run lh (B_hi reused) ----
#pragma unroll
                for (int mt = 0; mt < 2; ++mt)
                    ldsm4(a[mt], pAl + swz((uint32_t)((wm + mt * 16 + a_r) * 128 + kk * 32 + a_k)));
#pragma unroll
                for (int mt = 0; mt < 2; ++mt)
#pragma unroll
                    for (int g = 0; g < 4; ++g) {
                        mma16816(acc[mt][2 * g],     a[mt], &bh[g][0]);
                        mma16816(acc[mt][2 * g + 1], a[mt], &bh[g][2]);
                    }
            }
        }
        __syncthreads();
    }

    // ------------------------------ epilogue ---------------------------------
    const int erow = (lid >> 2);
    const int ecol = (lid & 3) * 2;

    if (MODE == 1) {
#pragma unroll
        for (int mt = 0; mt < 2; ++mt) {
#pragma unroll
            for (int nt = 0; nt < 8; ++nt) {
                const int col = bn + wn + nt * 8 + ecol;
                const int r0  = bm + wm + mt * 16 + erow;
                float2 v0 = make_float2(acc[mt][nt][0] * INV_YS, acc[mt][nt][1] * INV_YS);
                float2 v1 = make_float2(acc[mt][nt][2] * INV_YS, acc[mt][nt][3] * INV_YS);
                *(float2*)(out0 + (size_t)r0 * D_ + col)       = v0;
                *(float2*)(out0 + (size_t)(r0 + 8) * D_ + col) = v1;
            }
        }
    } else {
        __syncthreads();
        float bnd[15];
#pragma unroll
        for (int b0 = 0; b0 < 15; ++b0) bnd[b0] = s_bound[b0];
#pragma unroll
        for (int mt = 0; mt < 2; ++mt) {
#pragma unroll
            for (int nt = 0; nt < 8; ++nt) {
                const int col = bn + wn + nt * 8 + ecol;
#pragma unroll
                for (int half = 0; half < 2; ++half) {
                    const int r0 = bm + wm + mt * 16 + erow + half * 8;
                    float v0 = acc[mt][nt][half * 2 + 0];  // scaled y' = 2^20 y
                    float v1 = acc[mt][nt][half * 2 + 1];
                    int q0 = 0, q1 = 0;
#pragma unroll
                    for (int b0 = 0; b0 < 15; ++b0) {
                        q0 += (v0 > bnd[b0]) ? 1 : 0;
                        q1 += (v1 > bnd[b0]) ? 1 : 0;
                    }
                    float dl0 = (q0 > 0)  ? v0 - s_bound[q0 - 1] : 1e30f;
                    float dr0 = (q0 < 15) ? s_bound[q0] - v0     : 1e30f;
                    float dl1 = (q1 > 0)  ? v1 - s_bound[q1 - 1] : 1e30f;
                    float dr1 = (q1 < 15) ? s_bound[q1] - v1     : 1e30f;
                    bool n0 = fminf(dl0, dr0) < THR;
                    bool n1 = fminf(dl1, dr1) < THR;
                    repair_warp(v0, n0, r0, col,     xf, pif, lid);
                    repair_warp(v1, n1, r0, col + 1, xf, pif, lid);
                    if (n0) {
                        q0 = 0;
#pragma unroll
                        for (int b0 = 0; b0 < 15; ++b0) q0 += (v0 > bnd[b0]) ? 1 : 0;
                    }
                    if (n1) {
                        q1 = 0;
#pragma unroll
                        for (int b0 = 0; b0 < 15; ++b0) q1 += (v1 > bnd[b0]) ? 1 : 0;
                    }
                    const size_t off = (size_t)r0 * D_ + col;
                    *(uint32_t*)(g_yhhi + off) =
                        (uint32_t)s_chi[q0] | ((uint32_t)s_chi[q1] << 16);
                    if (write_idx) {
                        float2 f = make_float2((float)q0, (float)q1);
                        *(float2*)(out0 + off) = f;
                    }
                }
            }
        }
    }
}

// ---------------------------- prep kernels -----------------------------------
__global__ __launch_bounds__(256)
void k_split(const float* __restrict__ src,
             __half* __restrict__ hi, __half* __restrict__ lo)
{
    const size_t i = ((size_t)blockIdx.x * 256 + threadIdx.x) * 4;
    float4 v = *(const float4*)(src + i);
    float s0 = v.x * SCALE, s1 = v.y * SCALE, s2 = v.z * SCALE, s3 = v.w * SCALE;
    __half h0 = __float2half_rn(s0), h1 = __float2half_rn(s1);
    __half h2 = __float2half_rn(s2), h3 = __float2half_rn(s3);
    __half l0 = __float2half_rn(s0 - __half2float(h0));
    __half l1 = __float2half_rn(s1 - __half2float(h1));
    __half l2 = __float2half_rn(s2 - __half2float(h2));
    __half l3 = __float2half_rn(s3 - __half2float(h3));
    uint2 uh; uh.x = pack2(h0, h1); uh.y = pack2(h2, h3);
    uint2 ul; ul.x = pack2(l0, l1); ul.y = pack2(l2, l3);
    *(uint2*)(hi + i) = uh;
    *(uint2*)(lo + i) = ul;
}

__global__ __launch_bounds__(256)
void k_tsplit(const float* __restrict__ Pi)
{
    __shared__ float tile[32][33];
    const int bx = blockIdx.x * 32, by = blockIdx.y * 32;
    const int tx = threadIdx.x & 31, ty = threadIdx.x >> 5;
#pragma unroll
    for (int r = 0; r < 4; ++r)
        tile[ty + r * 8][tx] = Pi[(size_t)(by + ty + r * 8) * D_ + bx + tx];
    __syncthreads();
#pragma unroll
    for (int r = 0; r < 4; ++r) {
        float v = tile[tx][ty + r * 8] * SCALE;
        g_pthi[(size_t)(bx + ty + r * 8) * D_ + by + tx] = __float2half_rn(v);
    }
}

// ---------------------------- launch ------------------------------------------
extern "C" void kernel_launch(void* const* d_in, const int* in_sizes, int n_in,
                              void* d_out, int out_size)
{
    const float* x    = (const float*)d_in[0];
    const float* Pi   = (const float*)d_in[1];
    const float* cent = (const float*)d_in[2];

    float* out  = (float*)d_out;
    float* xhat = out;
    float* idxf = out + (size_t)N_ * D_;

    const long long total = (long long)N_ * D_;
    const int write_idx = ((long long)out_size >= 2 * total) ? 1 : 0;

    cudaFuncSetAttribute(tq_mma<0>, cudaFuncAttributeMaxDynamicSharedMemorySize, SMEM3);
    cudaFuncSetAttribute(tq_mma<1>, cudaFuncAttributeMaxDynamicSharedMemorySize, SMEM1);

    __half *xhi_p, *xlo_p, *phi_p, *plo_p;
    cudaGetSymbolAddress((void**)&xhi_p, g_xhi);
    cudaGetSymbolAddress((void**)&xlo_p, g_xlo);
    cudaGetSymbolAddress((void**)&phi_p, g_phi);
    cudaGetSymbolAddress((void**)&plo_p, g_plo);

    const int nblk = (int)(total / (4 * 256));                 // 16384
    k_split<<<nblk, 256>>>(x,  xhi_p, xlo_p);
    k_split<<<nblk, 256>>>(Pi, phi_p, plo_p);
    k_tsplit<<<dim3(D_ / 32, D_ / 32), 256>>>(Pi);

    dim3 grid(D_ / BN, N_ / BM);   // (16, 32)
    tq_mma<0><<<grid, NTH, SMEM3>>>(cent, idxf, write_idx, x, Pi);
    tq_mma<1><<<grid, NTH, SMEM1>>>(nullptr, xhat, 0, x, Pi);
}

// round 7
// speedup vs baseline: 4.4800x; 1.1070x over previous
#include <cuda_runtime.h>
#include <cuda_fp16.h>
#include <cstdint>
#include <cstddef>

// ============================================================================
// TurboQuantMSE via mma.sync fp16 (HMMA, sm_80 ISA — valid on plain sm_103).
// Both GEMMs run as SINGLE-product fp16 (operands scaled by 2^10).
// GEMM1's fp16 operand-rounding error (sigma ~6.2e-6 in y) is handled by an
// exact fp32 warp-cooperative repair of all values within THR=72 (2^-20
// units) of a quantization boundary (~2% of elements); repair memory traffic
// hides under other CTAs' tensor work. mma.sync is pipe-ceiling-bound on
// sm_103a (~43% tensor), so fewer MMAs == proportionally faster.
// ============================================================================

#define DEVFN __device__ __forceinline__

namespace {
constexpr int N_  = 4096;
constexpr int D_  = 4096;
constexpr int BM  = 128;
constexpr int BN  = 256;
constexpr int BKE = 64;                 // K elements per chunk (fp16)
constexpr int NCH = D_ / BKE;           // 64 chunks
constexpr int NTH = 512;                // 16 warps

constexpr float SCALE   = 1024.0f;             // 2^10, exact
constexpr float YSCALE  = 1048576.0f;          // 2^20, exact
constexpr float INV_YS  = 1.0f / 1048576.0f;   // exact power of two
constexpr float THR     = 72.0f;               // repair threshold (scaled units)

constexpr int A_BYTES = BM * 128;       // 16 KB
constexpr int B_BYTES = BN * 128;       // 32 KB
constexpr int STAGE   = A_BYTES + B_BYTES;     // 48 KB
constexpr int NSTG    = 4;
constexpr int SMEM_SZ = NSTG * STAGE;          // 192 KB
}

// -------- device scratch (allocation-free rule: device globals) -------------
__device__ __half g_xhi [(size_t)N_ * D_];
__device__ __half g_phi [(size_t)D_ * D_];
__device__ __half g_pthi[(size_t)D_ * D_];
__device__ __half g_yhhi[(size_t)N_ * D_];

// ---------------------------- PTX helpers -----------------------------------
DEVFN uint32_t smem_u32(const void* p) {
    uint32_t a;
    asm("{ .reg .u64 t; cvta.to.shared.u64 t, %1; cvt.u32.u64 %0, t; }" : "=r"(a) : "l"(p));
    return a;
}
DEVFN void cpasync16(uint32_t s, const void* g) {
    asm volatile("cp.async.cg.shared.global [%0], [%1], 16;" :: "r"(s), "l"(g));
}
#define CP_COMMIT() asm volatile("cp.async.commit_group;" ::: "memory")
#define CP_WAIT2()  asm volatile("cp.async.wait_group 2;" ::: "memory")
#define CP_WAIT0()  asm volatile("cp.async.wait_group 0;" ::: "memory")

DEVFN void ldsm4(uint32_t* r, uint32_t addr) {
    asm volatile("ldmatrix.sync.aligned.m8n8.x4.shared.b16 {%0,%1,%2,%3}, [%4];"
                 : "=r"(r[0]), "=r"(r[1]), "=r"(r[2]), "=r"(r[3]) : "r"(addr));
}
DEVFN void mma16816(float* c, const uint32_t* a, const uint32_t* b) {
    asm volatile(
        "mma.sync.aligned.m16n8k16.row.col.f32.f16.f16.f32 "
        "{%0,%1,%2,%3}, {%4,%5,%6,%7}, {%8,%9}, {%0,%1,%2,%3};"
        : "+f"(c[0]), "+f"(c[1]), "+f"(c[2]), "+f"(c[3])
        : "r"(a[0]), "r"(a[1]), "r"(a[2]), "r"(a[3]), "r"(b[0]), "r"(b[1]));
}
DEVFN uint32_t pack2(__half a, __half b) {
    return (uint32_t)__half_as_ushort(a) | ((uint32_t)__half_as_ushort(b) << 16);
}
DEVFN uint32_t swz(uint32_t off) { return off ^ ((off >> 3) & 0x70); }

// ---------------------------- staging loader ---------------------------------
template<int ROWS>
DEVFN void ld_op(uint32_t sdst, const __half* __restrict__ g,
                 int row0, int kc, int tid)
{
    const char* gb = (const char*)g + ((size_t)row0 * D_ + (size_t)kc * BKE) * 2;
    constexpr int NOPS = ROWS * 8;             // 16B ops
#pragma unroll
    for (int i = 0; i < NOPS / NTH; ++i) {
        int idx = tid + i * NTH;
        int r = idx >> 3;
        int c = (idx & 7) << 4;
        cpasync16(sdst + swz((uint32_t)(r * 128 + c)),
                  gb + (size_t)r * (D_ * 2) + c);
    }
}

DEVFN void stage_load(uint32_t sb, int s, int kc,
                      const __half* A, const __half* B, int bm, int bn, int tid)
{
    const uint32_t st = sb + s * STAGE;
    ld_op<BM>(st,           A, bm, kc, tid);
    ld_op<BN>(st + A_BYTES, B, bn, kc, tid);
}

// --------- warp-cooperative exact fp32 re-computation of y'[row,col] ---------
DEVFN void repair_warp(float& v, bool need, int row, int col,
                       const float* __restrict__ x, const float* __restrict__ Pi,
                       int lid)
{
    unsigned m = __ballot_sync(0xFFFFFFFFu, need);
    while (m) {
        int src = __ffs(m) - 1;
        m &= m - 1;
        int r = __shfl_sync(0xFFFFFFFFu, row, src);
        int c = __shfl_sync(0xFFFFFFFFu, col, src);
        const float* xr = x  + (size_t)r * D_;
        const float* pr = Pi + (size_t)c * D_;
        float s0 = 0.f, s1 = 0.f, s2 = 0.f, s3 = 0.f;
#pragma unroll 4
        for (int k = lid * 4; k < D_; k += 128) {
            float4 a = *(const float4*)(xr + k);
            float4 b = *(const float4*)(pr + k);
            s0 = fmaf(a.x, b.x, s0); s1 = fmaf(a.y, b.y, s1);
            s2 = fmaf(a.z, b.z, s2); s3 = fmaf(a.w, b.w, s3);
        }
        float part = (s0 + s1) + (s2 + s3);
#pragma unroll
        for (int o = 16; o; o >>= 1) part += __shfl_xor_sync(0xFFFFFFFFu, part, o);
        if (lid == src) v = part * YSCALE;
    }
}

// ---------------------------- main GEMM kernel -------------------------------
// MODE 0: GEMM1 (x_hi, Pi_hi)    -> quantize epilogue with boundary repair
// MODE 1: GEMM2 (yhat_hi, PiT_hi) -> fp32 store * 2^-20
template<int MODE>
__global__ __launch_bounds__(NTH, 1)
void tq_mma(const float* __restrict__ cent, float* __restrict__ out0, int write_idx,
            const float* __restrict__ xf, const float* __restrict__ pif)
{
    extern __shared__ char smem[];
    const uint32_t sb = smem_u32(smem);
    const int tid = threadIdx.x, wid = tid >> 5, lid = tid & 31;
    const int bm = blockIdx.y * BM;
    const int bn = blockIdx.x * BN;

    const __half* A = (MODE == 0) ? g_xhi : g_yhhi;
    const __half* B = (MODE == 0) ? g_phi : g_pthi;

    __shared__ float    s_bound[16];
    __shared__ uint16_t s_chi[16];
    if (MODE == 0) {
        if (tid < 16) {
            float cs = cent[tid] * SCALE;           // exact
            s_chi[tid] = __half_as_ushort(__float2half_rn(cs));
        }
        if (tid < 15) s_bound[tid] = (0.5f * (cent[tid] + cent[tid + 1])) * YSCALE;
    }

    // 16 warps: 4 (M) x 4 (N), each 32x64
    const int wm = (wid & 3) * 32;
    const int wn = (wid >> 2) * 64;

    const int a_r = lid & 15;
    const int a_k = (lid >> 4) << 4;
    const int b_r = (lid & 7) | ((lid >> 4) << 3);
    const int b_k = ((lid >> 3) & 1) << 4;

    float acc[2][8][4];
#pragma unroll
    for (int i = 0; i < 2; ++i)
#pragma unroll
        for (int j = 0; j < 8; ++j)
#pragma unroll
            for (int k = 0; k < 4; ++k) acc[i][j][k] = 0.0f;

    // prologue: prime 3 stages
#pragma unroll
    for (int s = 0; s < 3; ++s) {
        stage_load(sb, s, s, A, B, bm, bn, tid);
        CP_COMMIT();
    }

    for (int t = 0; t < NCH; ++t) {
        if (t + 3 < NCH) CP_WAIT2(); else CP_WAIT0();
        __syncthreads();
        if (t + 3 < NCH) {
            stage_load(sb, (t + 3) & (NSTG - 1), t + 3, A, B, bm, bn, tid);
            CP_COMMIT();
        }
        const uint32_t st = sb + (t & (NSTG - 1)) * STAGE;
        const uint32_t pA = st;
        const uint32_t pB = st + A_BYTES;

        uint32_t a[2][4], b[4][4];
#pragma unroll
        for (int kk = 0; kk < 4; ++kk) {
#pragma unroll
            for (int mt = 0; mt < 2; ++mt)
                ldsm4(a[mt], pA + swz((uint32_t)((wm + mt * 16 + a_r) * 128 + kk * 32 + a_k)));
#pragma unroll
            for (int g = 0; g < 4; ++g)
                ldsm4(b[g], pB + swz((uint32_t)((wn + g * 16 + b_r) * 128 + kk * 32 + b_k)));
#pragma unroll
            for (int mt = 0; mt < 2; ++mt)
#pragma unroll
                for (int g = 0; g < 4; ++g) {
                    mma16816(acc[mt][2 * g],     a[mt], &b[g][0]);
                    mma16816(acc[mt][2 * g + 1], a[mt], &b[g][2]);
                }
        }
    }
    __syncthreads();

    // ------------------------------ epilogue ---------------------------------
    const int erow = (lid >> 2);
    const int ecol = (lid & 3) * 2;

    if (MODE == 1) {
#pragma unroll
        for (int mt = 0; mt < 2; ++mt) {
#pragma unroll
            for (int nt = 0; nt < 8; ++nt) {
                const int col = bn + wn + nt * 8 + ecol;
                const int r0  = bm + wm + mt * 16 + erow;
                float2 v0 = make_float2(acc[mt][nt][0] * INV_YS, acc[mt][nt][1] * INV_YS);
                float2 v1 = make_float2(acc[mt][nt][2] * INV_YS, acc[mt][nt][3] * INV_YS);
                *(float2*)(out0 + (size_t)r0 * D_ + col)       = v0;
                *(float2*)(out0 + (size_t)(r0 + 8) * D_ + col) = v1;
            }
        }
    } else {
        float bnd[15];
#pragma unroll
        for (int b0 = 0; b0 < 15; ++b0) bnd[b0] = s_bound[b0];
#pragma unroll
        for (int mt = 0; mt < 2; ++mt) {
#pragma unroll
            for (int nt = 0; nt < 8; ++nt) {
                const int col = bn + wn + nt * 8 + ecol;
#pragma unroll
                for (int half = 0; half < 2; ++half) {
                    const int r0 = bm + wm + mt * 16 + erow + half * 8;
                    float v0 = acc[mt][nt][half * 2 + 0];  // scaled y' = 2^20 y
                    float v1 = acc[mt][nt][half * 2 + 1];
                    int q0 = 0, q1 = 0;
#pragma unroll
                    for (int b0 = 0; b0 < 15; ++b0) {
                        q0 += (v0 > bnd[b0]) ? 1 : 0;
                        q1 += (v1 > bnd[b0]) ? 1 : 0;
                    }
                    float dl0 = (q0 > 0)  ? v0 - s_bound[q0 - 1] : 1e30f;
                    float dr0 = (q0 < 15) ? s_bound[q0] - v0     : 1e30f;
                    float dl1 = (q1 > 0)  ? v1 - s_bound[q1 - 1] : 1e30f;
                    float dr1 = (q1 < 15) ? s_bound[q1] - v1     : 1e30f;
                    bool n0 = fminf(dl0, dr0) < THR;
                    bool n1 = fminf(dl1, dr1) < THR;
                    repair_warp(v0, n0, r0, col,     xf, pif, lid);
                    repair_warp(v1, n1, r0, col + 1, xf, pif, lid);
                    if (n0) {
                        q0 = 0;
#pragma unroll
                        for (int b0 = 0; b0 < 15; ++b0) q0 += (v0 > bnd[b0]) ? 1 : 0;
                    }
                    if (n1) {
                        q1 = 0;
#pragma unroll
                        for (int b0 = 0; b0 < 15; ++b0) q1 += (v1 > bnd[b0]) ? 1 : 0;
                    }
                    const size_t off = (size_t)r0 * D_ + col;
                    *(uint32_t*)(g_yhhi + off) =
                        (uint32_t)s_chi[q0] | ((uint32_t)s_chi[q1] << 16);
                    if (write_idx) {
                        float2 f = make_float2((float)q0, (float)q1);
                        *(float2*)(out0 + off) = f;
                    }
                }
            }
        }
    }
}

// ---------------------------- prep kernels -----------------------------------
__global__ __launch_bounds__(256)
void k_cvt(const float* __restrict__ src, __half* __restrict__ hi)
{
    const size_t i = ((size_t)blockIdx.x * 256 + threadIdx.x) * 4;
    float4 v = *(const float4*)(src + i);
    uint2 uh;
    uh.x = pack2(__float2half_rn(v.x * SCALE), __float2half_rn(v.y * SCALE));
    uh.y = pack2(__float2half_rn(v.z * SCALE), __float2half_rn(v.w * SCALE));
    *(uint2*)(hi + i) = uh;
}

__global__ __launch_bounds__(256)
void k_tcvt(const float* __restrict__ Pi)
{
    __shared__ float tile[32][33];
    const int bx = blockIdx.x * 32, by = blockIdx.y * 32;
    const int tx = threadIdx.x & 31, ty = threadIdx.x >> 5;
#pragma unroll
    for (int r = 0; r < 4; ++r)
        tile[ty + r * 8][tx] = Pi[(size_t)(by + ty + r * 8) * D_ + bx + tx];
    __syncthreads();
#pragma unroll
    for (int r = 0; r < 4; ++r) {
        float v = tile[tx][ty + r * 8] * SCALE;
        g_pthi[(size_t)(bx + ty + r * 8) * D_ + by + tx] = __float2half_rn(v);
    }
}

// ---------------------------- launch ------------------------------------------
extern "C" void kernel_launch(void* const* d_in, const int* in_sizes, int n_in,
                              void* d_out, int out_size)
{
    const float* x    = (const float*)d_in[0];
    const float* Pi   = (const float*)d_in[1];
    const float* cent = (const float*)d_in[2];

    float* out  = (float*)d_out;
    float* xhat = out;
    float* idxf = out + (size_t)N_ * D_;

    const long long total = (long long)N_ * D_;
    const int write_idx = ((long long)out_size >= 2 * total) ? 1 : 0;

    cudaFuncSetAttribute(tq_mma<0>, cudaFuncAttributeMaxDynamicSharedMemorySize, SMEM_SZ);
    cudaFuncSetAttribute(tq_mma<1>, cudaFuncAttributeMaxDynamicSharedMemorySize, SMEM_SZ);

    __half *xhi_p, *phi_p;
    cudaGetSymbolAddress((void**)&xhi_p, g_xhi);
    cudaGetSymbolAddress((void**)&phi_p, g_phi);

    const int nblk = (int)(total / (4 * 256));                 // 16384
    k_cvt<<<nblk, 256>>>(x,  xhi_p);
    k_cvt<<<nblk, 256>>>(Pi, phi_p);
    k_tcvt<<<dim3(D_ / 32, D_ / 32), 256>>>(Pi);

    dim3 grid(D_ / BN, N_ / BM);   // (16, 32)
    tq_mma<0><<<grid, NTH, SMEM_SZ>>>(cent, idxf, write_idx, x, Pi);
    tq_mma<1><<<grid, NTH, SMEM_SZ>>>(nullptr, xhat, 0, x, Pi);
}

// round 8
// speedup vs baseline: 7.4978x; 1.6736x over previous
#include <cuda_runtime.h>
#include <cuda_fp16.h>
#include <cstdint>
#include <cstddef>

// ============================================================================
// TurboQuantMSE via mma.sync fp16 (HMMA, sm_80 ISA — valid on plain sm_103).
// Both GEMMs are SINGLE-product fp16 (operands scaled by 2^10).
// GEMM1 epilogue flags values within THR=16 (2^-20 units, ~5 sigma of the
// fp16 operand-rounding residual) of a quantization boundary (~0.45%) into a
// global list; a separate repair kernel recomputes those dots exactly in
// fp32 and patches idx + yhat before GEMM2 runs.
// ============================================================================

#define DEVFN __device__ __forceinline__

namespace {
constexpr int N_  = 4096;
constexpr int D_  = 4096;
constexpr int BM  = 128;
constexpr int BN  = 256;
constexpr int BKE = 64;                 // K elements per chunk (fp16)
constexpr int NCH = D_ / BKE;           // 64 chunks
constexpr int NTH = 512;                // 16 warps

constexpr float SCALE   = 1024.0f;             // 2^10, exact
constexpr float YSCALE  = 1048576.0f;          // 2^20, exact
constexpr float INV_YS  = 1.0f / 1048576.0f;   // exact power of two
constexpr float THR     = 16.0f;               // flag threshold (scaled units)

constexpr int A_BYTES = BM * 128;       // 16 KB
constexpr int B_BYTES = BN * 128;       // 32 KB
constexpr int STAGE   = A_BYTES + B_BYTES;     // 48 KB
constexpr int NSTG    = 4;
constexpr int SMEM_SZ = NSTG * STAGE;          // 192 KB

constexpr uint32_t FLAG_CAP = 1u << 22;        // 4M entries (16 MB)
}

// -------- device scratch (allocation-free rule: device globals) -------------
__device__ __half    g_xhi [(size_t)N_ * D_];
__device__ __half    g_phi [(size_t)D_ * D_];
__device__ __half    g_pthi[(size_t)D_ * D_];
__device__ __half    g_yhhi[(size_t)N_ * D_];
__device__ uint32_t  g_flags[FLAG_CAP];
__device__ uint32_t  g_flagcnt;

// ---------------------------- PTX helpers -----------------------------------
DEVFN uint32_t smem_u32(const void* p) {
    uint32_t a;
    asm("{ .reg .u64 t; cvta.to.shared.u64 t, %1; cvt.u32.u64 %0, t; }" : "=r"(a) : "l"(p));
    return a;
}
DEVFN void cpasync16(uint32_t s, const void* g) {
    asm volatile("cp.async.cg.shared.global [%0], [%1], 16;" :: "r"(s), "l"(g));
}
#define CP_COMMIT() asm volatile("cp.async.commit_group;" ::: "memory")
#define CP_WAIT2()  asm volatile("cp.async.wait_group 2;" ::: "memory")
#define CP_WAIT0()  asm volatile("cp.async.wait_group 0;" ::: "memory")

DEVFN void ldsm4(uint32_t* r, uint32_t addr) {
    asm volatile("ldmatrix.sync.aligned.m8n8.x4.shared.b16 {%0,%1,%2,%3}, [%4];"
                 : "=r"(r[0]), "=r"(r[1]), "=r"(r[2]), "=r"(r[3]) : "r"(addr));
}
DEVFN void mma16816(float* c, const uint32_t* a, const uint32_t* b) {
    asm volatile(
        "mma.sync.aligned.m16n8k16.row.col.f32.f16.f16.f32 "
        "{%0,%1,%2,%3}, {%4,%5,%6,%7}, {%8,%9}, {%0,%1,%2,%3};"
        : "+f"(c[0]), "+f"(c[1]), "+f"(c[2]), "+f"(c[3])
        : "r"(a[0]), "r"(a[1]), "r"(a[2]), "r"(a[3]), "r"(b[0]), "r"(b[1]));
}
DEVFN uint32_t pack2(__half a, __half b) {
    return (uint32_t)__half_as_ushort(a) | ((uint32_t)__half_as_ushort(b) << 16);
}
DEVFN uint32_t swz(uint32_t off) { return off ^ ((off >> 3) & 0x70); }

// warp-aggregated append of (row<<12 | col) into the flag list
DEVFN void append_flag(bool need, uint32_t item, int lid) {
    unsigned m = __ballot_sync(0xFFFFFFFFu, need);
    if (!m) return;
    int leader = __ffs(m) - 1;
    uint32_t base = 0;
    if (lid == leader) base = atomicAdd(&g_flagcnt, (uint32_t)__popc(m));
    base = __shfl_sync(0xFFFFFFFFu, base, leader);
    if (need) {
        uint32_t off = base + (uint32_t)__popc(m & ((1u << lid) - 1u));
        if (off < FLAG_CAP) g_flags[off] = item;
    }
}

// ---------------------------- staging loader ---------------------------------
template<int ROWS>
DEVFN void ld_op(uint32_t sdst, const __half* __restrict__ g,
                 int row0, int kc, int tid)
{
    const char* gb = (const char*)g + ((size_t)row0 * D_ + (size_t)kc * BKE) * 2;
    constexpr int NOPS = ROWS * 8;             // 16B ops
#pragma unroll
    for (int i = 0; i < NOPS / NTH; ++i) {
        int idx = tid + i * NTH;
        int r = idx >> 3;
        int c = (idx & 7) << 4;
        cpasync16(sdst + swz((uint32_t)(r * 128 + c)),
                  gb + (size_t)r * (D_ * 2) + c);
    }
}

DEVFN void stage_load(uint32_t sb, int s, int kc,
                      const __half* A, const __half* B, int bm, int bn, int tid)
{
    const uint32_t st = sb + s * STAGE;
    ld_op<BM>(st,           A, bm, kc, tid);
    ld_op<BN>(st + A_BYTES, B, bn, kc, tid);
}

// ---------------------------- main GEMM kernel -------------------------------
// MODE 0: GEMM1 (x_hi, Pi_hi)     -> quantize epilogue, flag boundary cases
// MODE 1: GEMM2 (yhat_hi, PiT_hi) -> fp32 store * 2^-20
template<int MODE>
__global__ __launch_bounds__(NTH, 1)
void tq_mma(const float* __restrict__ cent, float* __restrict__ out0, int write_idx)
{
    extern __shared__ char smem[];
    const uint32_t sb = smem_u32(smem);
    const int tid = threadIdx.x, wid = tid >> 5, lid = tid & 31;
    const int bm = blockIdx.y * BM;
    const int bn = blockIdx.x * BN;

    const __half* A = (MODE == 0) ? g_xhi : g_yhhi;
    const __half* B = (MODE == 0) ? g_phi : g_pthi;

    __shared__ float    s_bound[16];
    __shared__ uint16_t s_chi[16];
    if (MODE == 0) {
        if (tid < 16) {
            float cs = cent[tid] * SCALE;           // exact
            s_chi[tid] = __half_as_ushort(__float2half_rn(cs));
        }
        if (tid < 15) s_bound[tid] = (0.5f * (cent[tid] + cent[tid + 1])) * YSCALE;
    }

    // 16 warps: 4 (M) x 4 (N), each 32x64
    const int wm = (wid & 3) * 32;
    const int wn = (wid >> 2) * 64;

    const int a_r = lid & 15;
    const int a_k = (lid >> 4) << 4;
    const int b_r = (lid & 7) | ((lid >> 4) << 3);
    const int b_k = ((lid >> 3) & 1) << 4;

    float acc[2][8][4];
#pragma unroll
    for (int i = 0; i < 2; ++i)
#pragma unroll
        for (int j = 0; j < 8; ++j)
#pragma unroll
            for (int k = 0; k < 4; ++k) acc[i][j][k] = 0.0f;

#pragma unroll
    for (int s = 0; s < 3; ++s) {
        stage_load(sb, s, s, A, B, bm, bn, tid);
        CP_COMMIT();
    }

    for (int t = 0; t < NCH; ++t) {
        if (t + 3 < NCH) CP_WAIT2(); else CP_WAIT0();
        __syncthreads();
        if (t + 3 < NCH) {
            stage_load(sb, (t + 3) & (NSTG - 1), t + 3, A, B, bm, bn, tid);
            CP_COMMIT();
        }
        const uint32_t st = sb + (t & (NSTG - 1)) * STAGE;
        const uint32_t pA = st;
        const uint32_t pB = st + A_BYTES;

        uint32_t a[2][4], b[4][4];
#pragma unroll
        for (int kk = 0; kk < 4; ++kk) {
#pragma unroll
            for (int mt = 0; mt < 2; ++mt)
                ldsm4(a[mt], pA + swz((uint32_t)((wm + mt * 16 + a_r) * 128 + kk * 32 + a_k)));
#pragma unroll
            for (int g = 0; g < 4; ++g)
                ldsm4(b[g], pB + swz((uint32_t)((wn + g * 16 + b_r) * 128 + kk * 32 + b_k)));
#pragma unroll
            for (int mt = 0; mt < 2; ++mt)
#pragma unroll
                for (int g = 0; g < 4; ++g) {
                    mma16816(acc[mt][2 * g],     a[mt], &b[g][0]);
                    mma16816(acc[mt][2 * g + 1], a[mt], &b[g][2]);
                }
        }
    }
    __syncthreads();

    // ------------------------------ epilogue ---------------------------------
    const int erow = (lid >> 2);
    const int ecol = (lid & 3) * 2;

    if (MODE == 1) {
#pragma unroll
        for (int mt = 0; mt < 2; ++mt) {
#pragma unroll
            for (int nt = 0; nt < 8; ++nt) {
                const int col = bn + wn + nt * 8 + ecol;
                const int r0  = bm + wm + mt * 16 + erow;
                float2 v0 = make_float2(acc[mt][nt][0] * INV_YS, acc[mt][nt][1] * INV_YS);
                float2 v1 = make_float2(acc[mt][nt][2] * INV_YS, acc[mt][nt][3] * INV_YS);
                *(float2*)(out0 + (size_t)r0 * D_ + col)       = v0;
                *(float2*)(out0 + (size_t)(r0 + 8) * D_ + col) = v1;
            }
        }
    } else {
        float bnd[15];
#pragma unroll
        for (int b0 = 0; b0 < 15; ++b0) bnd[b0] = s_bound[b0];
#pragma unroll
        for (int mt = 0; mt < 2; ++mt) {
#pragma unroll
            for (int nt = 0; nt < 8; ++nt) {
                const int col = bn + wn + nt * 8 + ecol;
#pragma unroll
                for (int half = 0; half < 2; ++half) {
                    const int r0 = bm + wm + mt * 16 + erow + half * 8;
                    float v0 = acc[mt][nt][half * 2 + 0];  // scaled y' = 2^20 y
                    float v1 = acc[mt][nt][half * 2 + 1];
                    int q0 = 0, q1 = 0;
#pragma unroll
                    for (int b0 = 0; b0 < 15; ++b0) {
                        q0 += (v0 > bnd[b0]) ? 1 : 0;
                        q1 += (v1 > bnd[b0]) ? 1 : 0;
                    }
                    float dl0 = (q0 > 0)  ? v0 - s_bound[q0 - 1] : 1e30f;
                    float dr0 = (q0 < 15) ? s_bound[q0] - v0     : 1e30f;
                    float dl1 = (q1 > 0)  ? v1 - s_bound[q1 - 1] : 1e30f;
                    float dr1 = (q1 < 15) ? s_bound[q1] - v1     : 1e30f;
                    bool n0 = fminf(dl0, dr0) < THR;
                    bool n1 = fminf(dl1, dr1) < THR;
                    append_flag(n0, ((uint32_t)r0 << 12) | (uint32_t)col,       lid);
                    append_flag(n1, ((uint32_t)r0 << 12) | (uint32_t)(col + 1), lid);
                    const size_t off = (size_t)r0 * D_ + col;
                    *(uint32_t*)(g_yhhi + off) =
                        (uint32_t)s_chi[q0] | ((uint32_t)s_chi[q1] << 16);
                    if (write_idx) {
                        float2 f = make_float2((float)q0, (float)q1);
                        *(float2*)(out0 + off) = f;
                    }
                }
            }
        }
    }
}

// ---------------------------- repair kernel -----------------------------------
__global__ __launch_bounds__(256)
void k_repair(const float* __restrict__ x, const float* __restrict__ Pi,
              const float* __restrict__ cent, float* __restrict__ idxf,
              int write_idx)
{
    const int lid = threadIdx.x & 31;
    const int wgid = (blockIdx.x * blockDim.x + threadIdx.x) >> 5;
    const int nw   = (gridDim.x * blockDim.x) >> 5;

    float bnd[15];
    float c16[16];
#pragma unroll
    for (int i = 0; i < 16; ++i) c16[i] = __ldg(cent + i);
#pragma unroll
    for (int i = 0; i < 15; ++i) bnd[i] = 0.5f * (c16[i] + c16[i + 1]);

    uint32_t cnt = g_flagcnt;
    if (cnt > FLAG_CAP) cnt = FLAG_CAP;

    for (uint32_t e = wgid; e < cnt; e += (uint32_t)nw) {
        uint32_t item = g_flags[e];
        int r = (int)(item >> 12);
        int c = (int)(item & 4095u);
        const float* xr = x  + (size_t)r * D_;
        const float* pr = Pi + (size_t)c * D_;
        float s0 = 0.f, s1 = 0.f, s2 = 0.f, s3 = 0.f;
#pragma unroll 4
        for (int k = lid * 4; k < D_; k += 128) {
            float4 a = *(const float4*)(xr + k);
            float4 b = *(const float4*)(pr + k);
            s0 = fmaf(a.x, b.x, s0); s1 = fmaf(a.y, b.y, s1);
            s2 = fmaf(a.z, b.z, s2); s3 = fmaf(a.w, b.w, s3);
        }
        float v = (s0 + s1) + (s2 + s3);
#pragma unroll
        for (int o = 16; o; o >>= 1) v += __shfl_xor_sync(0xFFFFFFFFu, v, o);
        if (lid == 0) {
            int q = 0;
#pragma unroll
            for (int b0 = 0; b0 < 15; ++b0) q += (v > bnd[b0]) ? 1 : 0;
            const size_t off = (size_t)r * D_ + c;
            g_yhhi[off] = __float2half_rn(c16[q] * SCALE);
            if (write_idx) idxf[off] = (float)q;
        }
    }
}

__global__ void k_zero() { if (threadIdx.x == 0) g_flagcnt = 0; }

// ---------------------------- prep kernels -----------------------------------
__global__ __launch_bounds__(256)
void k_cvt(const float* __restrict__ src, __half* __restrict__ hi)
{
    const size_t i = ((size_t)blockIdx.x * 256 + threadIdx.x) * 4;
    float4 v = *(const float4*)(src + i);
    uint2 uh;
    uh.x = pack2(__float2half_rn(v.x * SCALE), __float2half_rn(v.y * SCALE));
    uh.y = pack2(__float2half_rn(v.z * SCALE), __float2half_rn(v.w * SCALE));
    *(uint2*)(hi + i) = uh;
}

__global__ __launch_bounds__(256)
void k_tcvt(const float* __restrict__ Pi)
{
    __shared__ float tile[32][33];
    const int bx = blockIdx.x * 32, by = blockIdx.y * 32;
    const int tx = threadIdx.x & 31, ty = threadIdx.x >> 5;
#pragma unroll
    for (int r = 0; r < 4; ++r)
        tile[ty + r * 8][tx] = Pi[(size_t)(by + ty + r * 8) * D_ + bx + tx];
    __syncthreads();
#pragma unroll
    for (int r = 0; r < 4; ++r) {
        float v = tile[tx][ty + r * 8] * SCALE;
        g_pthi[(size_t)(bx + ty + r * 8) * D_ + by + tx] = __float2half_rn(v);
    }
}

// ---------------------------- launch ------------------------------------------
extern "C" void kernel_launch(void* const* d_in, const int* in_sizes, int n_in,
                              void* d_out, int out_size)
{
    const float* x    = (const float*)d_in[0];
    const float* Pi   = (const float*)d_in[1];
    const float* cent = (const float*)d_in[2];

    float* out  = (float*)d_out;
    float* xhat = out;
    float* idxf = out + (size_t)N_ * D_;

    const long long total = (long long)N_ * D_;
    const int write_idx = ((long long)out_size >= 2 * total) ? 1 : 0;

    cudaFuncSetAttribute(tq_mma<0>, cudaFuncAttributeMaxDynamicSharedMemorySize, SMEM_SZ);
    cudaFuncSetAttribute(tq_mma<1>, cudaFuncAttributeMaxDynamicSharedMemorySize, SMEM_SZ);

    __half *xhi_p, *phi_p;
    cudaGetSymbolAddress((void**)&xhi_p, g_xhi);
    cudaGetSymbolAddress((void**)&phi_p, g_phi);

    k_zero<<<1, 32>>>();
    const int nblk = (int)(total / (4 * 256));                 // 16384
    k_cvt<<<nblk, 256>>>(x,  xhi_p);
    k_cvt<<<nblk, 256>>>(Pi, phi_p);
    k_tcvt<<<dim3(D_ / 32, D_ / 32), 256>>>(Pi);

    dim3 grid(D_ / BN, N_ / BM);   // (16, 32)
    tq_mma<0><<<grid, NTH, SMEM_SZ>>>(cent, idxf, write_idx);
    k_repair<<<2048, 256>>>(x, Pi, cent, idxf, write_idx);
    tq_mma<1><<<grid, NTH, SMEM_SZ>>>(nullptr, xhat, 0);
}